// round 6
// baseline (speedup 1.0000x reference)
#include <cuda_runtime.h>
#include <math.h>

// Problem constants
#define V_ 10000
#define H_ 512
#define L_ 2
#define S_ 128
#define B_ 128
#define M_ (S_*B_)
#define BH_ (B_*H_)
#define NBLK 128          // persistent recurrence grid (<= 148 SMs -> co-resident)

// ---------------------------------------------------------------------------
// Device scratch (static globals; no allocation anywhere)
// All recurrence-adjacent tensors use transposed [t][j][b] layout so that
// warp lanes (= batch b) are contiguous in memory.
// ---------------------------------------------------------------------------
__device__ float g_X [(size_t)S_*H_*B_];   // X^T  [t][j][b]  (32 MB)
__device__ float g_H1[(size_t)S_*H_*B_];   // H1^T [t][j][b]
__device__ float g_H2[(size_t)S_*H_*B_];   // H2^T [t][j][b]
__device__ float g_P [2][8*H_*B_];         // split-K partials [buf][sp][j][b]
__device__ float g_Wt[L_*H_*H_];           // W_hh transposed, [l][k][j]
__device__ unsigned g_bar;                 // grid barrier counter

// ---------------------------------------------------------------------------
// f32x2 packed helpers (Blackwell: fma.rn.f32x2 — 2 fp32 FMAs per issue)
// ---------------------------------------------------------------------------
__device__ __forceinline__ unsigned long long pack2(float x, float y) {
    unsigned long long r;
    asm("mov.b64 %0, {%1,%2};" : "=l"(r) : "f"(x), "f"(y));
    return r;
}
__device__ __forceinline__ float2 unpack2(unsigned long long v) {
    float2 r;
    asm("mov.b64 {%0,%1}, %2;" : "=f"(r.x), "=f"(r.y) : "l"(v));
    return r;
}
__device__ __forceinline__ void fma2(unsigned long long& d,
                                     unsigned long long a, unsigned long long b) {
    asm("fma.rn.f32x2 %0, %1, %2, %0;" : "+l"(d) : "l"(a), "l"(b));
}
// load 16B from smem directly into two packed b64 operands
__device__ __forceinline__ void lds128_u64(unsigned long long& a,
                                           unsigned long long& b, const float* p) {
    unsigned addr = (unsigned)__cvta_generic_to_shared(p);
    asm volatile("ld.shared.v2.u64 {%0,%1}, [%2];" : "=l"(a), "=l"(b) : "r"(addr));
}

// ---------------------------------------------------------------------------
// W_hh transpose: g_Wt[l][k*H + j] = W_hh[l][j*H + k]
// ---------------------------------------------------------------------------
__global__ void transpose_whh_kernel(const float* __restrict__ Whh) {
    int idx = blockIdx.x * blockDim.x + threadIdx.x;
    int l = idx >> 18;
    int r = idx & (H_*H_ - 1);
    int k = r >> 9;
    int j = r & (H_ - 1);
    g_Wt[idx] = __ldg(&Whh[l*H_*H_ + j*H_ + k]);
}

__global__ void bar_reset_kernel() { g_bar = 0u; }

// ---------------------------------------------------------------------------
// Persistent recurrence kernel: one launch covers all S=128 steps of a layer.
// Block (g,u,s): g = batch group of 32 (4), u = j-tile of 128 (4),
//                s = k-slice of 64 (8)  -> 128 blocks, one per SM.
// W tile (64k x 128j) lives in smem for the whole kernel.
// Step t:
//   Phase R: h_{t-1}[b in g][j in slice s] = tanh(bias + sum_sp P_prev[sp])
//            (x[t-1] is already folded into P_prev[0]); u==0 writes Ht.
//   Phase C: P_cur[s][j in u][b in g] += sum_{k in s} h*W   (FFMA2)
//            s==0 additionally adds x[t] so Phase R stays pure.
//   Grid barrier (threadfence + atomicAdd + acquire poll on monotonic counter).
// ---------------------------------------------------------------------------
__global__ __launch_bounds__(256) void rec_persistent_kernel(
    const float* __restrict__ Xt,     // [S][H][B]
    const float* __restrict__ Wt,     // [H][H] (k-major) for this layer
    const float* __restrict__ bias,   // [H]
    const float* __restrict__ h0,     // [B][H] initial hidden
    float* __restrict__ Pb0, float* __restrict__ Pb1,
    float* __restrict__ Ht,           // [S][H][B]
    float* __restrict__ hfinal)       // [B][H]
{
    __shared__ float Ws[64][128];     // 32 KB, resident all steps
    __shared__ float hs[64][32];      // h tile [k][b]
    __shared__ float bs[64];

    const int tid = threadIdx.x;
    const int bid = blockIdx.x;
    const int g = bid & 3;
    const int u = (bid >> 2) & 3;
    const int s = bid >> 4;

    // Load W tile (rows k = s*64.., cols j = u*128..)
    {
        const float* wsrc = Wt + (size_t)(s*64)*H_ + u*128;
        for (int i = tid; i < 64*32; i += 256) {
            int r = i >> 5, c4 = (i & 31) * 4;
            *(float4*)&Ws[r][c4] = *(const float4*)(wsrc + (size_t)r*H_ + c4);
        }
        for (int i = tid; i < 64; i += 256) bs[i] = bias[s*64 + i];
    }
    __syncthreads();

    const int lane  = tid & 31;       // local batch
    const int w     = tid >> 5;       // warp id
    const int bglob = g*32 + lane;
    const int jloc  = w * 16;         // Phase C j sub-range within u-tile
    const int jglob = u*128 + jloc;

    unsigned long long acc[8];

    for (int t = 0; t < S_; t++) {
        const float* Pp = (t & 1) ? Pb0 : Pb1;
        float*       Pc = (t & 1) ? Pb1 : Pb0;

        // ---- Phase R: materialize h_{t-1}[b][k-slice s] into hs[k][b] ----
        if (t == 0) {
            #pragma unroll
            for (int q = 0; q < 8; q++) {
                int jj = w*8 + q;
                hs[jj][lane] = h0[(size_t)bglob*H_ + s*64 + jj];
            }
        } else {
            #pragma unroll
            for (int q = 0; q < 8; q++) {
                int jj = w*8 + q;
                size_t off = (size_t)(s*64 + jj)*B_ + bglob;
                float v = bs[jj];
                #pragma unroll
                for (int sp = 0; sp < 8; sp++)
                    v += Pp[(size_t)sp*H_*B_ + off];
                v = tanhf(v);
                hs[jj][lane] = v;
                if (u == 0) Ht[(size_t)(t-1)*H_*B_ + off] = v;
            }
        }
        __syncthreads();

        // ---- Phase C: partial matmul over this k-slice (FFMA2) ----
        #pragma unroll
        for (int p = 0; p < 8; p++) acc[p] = 0ull;

        #pragma unroll 4
        for (int k = 0; k < 64; k++) {
            float hv = hs[k][lane];
            unsigned long long hp = pack2(hv, hv);
            unsigned long long w0,w1,w2,w3,w4,w5,w6,w7;
            lds128_u64(w0, w1, &Ws[k][jloc]);
            lds128_u64(w2, w3, &Ws[k][jloc + 4]);
            lds128_u64(w4, w5, &Ws[k][jloc + 8]);
            lds128_u64(w6, w7, &Ws[k][jloc + 12]);
            fma2(acc[0], hp, w0); fma2(acc[1], hp, w1);
            fma2(acc[2], hp, w2); fma2(acc[3], hp, w3);
            fma2(acc[4], hp, w4); fma2(acc[5], hp, w5);
            fma2(acc[6], hp, w6); fma2(acc[7], hp, w7);
        }

        // store partial (coalesced over b); s==0 folds in x[t]
        {
            float* pdst = Pc + (size_t)s*H_*B_ + (size_t)jglob*B_ + bglob;
            const float* xsrc = Xt + (size_t)t*H_*B_ + (size_t)jglob*B_ + bglob;
            #pragma unroll
            for (int p = 0; p < 8; p++) {
                float2 v = unpack2(acc[p]);
                if (s == 0) {
                    v.x += xsrc[(size_t)(2*p)*B_];
                    v.y += xsrc[(size_t)(2*p+1)*B_];
                }
                pdst[(size_t)(2*p)*B_]   = v.x;
                pdst[(size_t)(2*p+1)*B_] = v.y;
            }
        }

        // ---- grid barrier ----
        __syncthreads();
        if (tid == 0) {
            __threadfence();
            atomicAdd(&g_bar, 1u);
            unsigned target = (unsigned)(t + 1) * NBLK;
            unsigned v;
            do {
                asm volatile("ld.acquire.gpu.u32 %0, [%1];"
                             : "=r"(v) : "l"(&g_bar));
            } while (v < target);
        }
        __syncthreads();
    }

    // ---- epilogue: h_{S-1} (u==0 blocks only) ----
    if (u == 0) {
        const float* Pl = ((S_-1) & 1) ? Pb1 : Pb0;
        #pragma unroll
        for (int q = 0; q < 8; q++) {
            int jj = w*8 + q;
            size_t off = (size_t)(s*64 + jj)*B_ + bglob;
            float v = bs[jj];
            #pragma unroll
            for (int sp = 0; sp < 8; sp++)
                v += Pl[(size_t)sp*H_*B_ + off];
            v = tanhf(v);
            Ht[(size_t)(S_-1)*H_*B_ + off] = v;
            hfinal[(size_t)bglob*H_ + s*64 + jj] = v;
        }
    }
}

// ---------------------------------------------------------------------------
// fp32 SGEMM with FFMA2 inner loop.
//   amode 0: A row-major [m][K], optional row gather
//   amode 1: A in [t][k][b] layout (our H^T / X^T tensors); m-tile == one t
//   cmode 0: C row-major [m][N] (+bias, N-guarded; N % 8 == 0)
//   cmode 1: C transposed [t][n][b] (full tiles, N == H)
// BM=BN=128, BK=8, 256 threads, 8x8 micro-tile, register prefetch.
// ---------------------------------------------------------------------------
__global__ __launch_bounds__(256) void sgemm2_kernel(
    const float* __restrict__ A,
    const int*   __restrict__ gather,
    const float* __restrict__ Bm,
    const float* __restrict__ bias,
    float*       __restrict__ C,
    int N, int K, int amode, int cmode)
{
    __shared__ float As[8][128];
    __shared__ float Bs[8][128];

    const int tid = threadIdx.x;
    const int bm = blockIdx.y * 128;
    const int bn = blockIdx.x * 128;

    // A loader
    const float* Ap;
    int a_r, a_c4;
    if (amode == 0) {
        a_r  = tid >> 1;            // m within tile
        a_c4 = (tid & 1) * 4;       // k
        int am = bm + a_r;
        int arow = gather ? gather[am] : am;
        Ap = A + (size_t)arow * K + a_c4;
    } else {
        a_r  = tid >> 5;            // k row 0..7
        a_c4 = (tid & 31) * 4;      // b
        Ap = A + (size_t)(bm >> 7) * K * B_ + (size_t)a_r * B_ + a_c4;
    }
    const int b_r = tid >> 1, b_c4 = (tid & 1) * 4;
    int nrow = bn + b_r; if (nrow >= N) nrow = N - 1;  // clamp, excluded at store
    const float* Bp = Bm + (size_t)nrow * K + b_c4;

    float4 areg = *(const float4*)Ap;
    float4 breg = *(const float4*)Bp;

    const int tx = tid & 15, ty = tid >> 4;
    unsigned long long acc[8][4];
    #pragma unroll
    for (int i = 0; i < 8; i++)
        #pragma unroll
        for (int p = 0; p < 4; p++) acc[i][p] = 0ull;

    for (int kt = 0; kt < K; kt += 8) {
        if (amode == 0) {
            As[a_c4+0][a_r] = areg.x; As[a_c4+1][a_r] = areg.y;
            As[a_c4+2][a_r] = areg.z; As[a_c4+3][a_r] = areg.w;
        } else {
            *(float4*)&As[a_r][a_c4] = areg;
        }
        Bs[b_c4+0][b_r] = breg.x; Bs[b_c4+1][b_r] = breg.y;
        Bs[b_c4+2][b_r] = breg.z; Bs[b_c4+3][b_r] = breg.w;
        __syncthreads();

        if (kt + 8 < K) {
            areg = (amode == 0) ? *(const float4*)(Ap + kt + 8)
                                : *(const float4*)(Ap + (size_t)(kt + 8) * B_);
            breg = *(const float4*)(Bp + kt + 8);
        }

        #pragma unroll
        for (int kk = 0; kk < 8; kk++) {
            float a[8];
            *(float4*)(a)     = *(const float4*)&As[kk][ty*8];
            *(float4*)(a + 4) = *(const float4*)&As[kk][ty*8 + 4];
            unsigned long long bp0, bp1, bp2, bp3;
            lds128_u64(bp0, bp1, &Bs[kk][tx*8]);
            lds128_u64(bp2, bp3, &Bs[kk][tx*8 + 4]);
            #pragma unroll
            for (int i = 0; i < 8; i++) {
                unsigned long long ap = pack2(a[i], a[i]);
                fma2(acc[i][0], ap, bp0);
                fma2(acc[i][1], ap, bp1);
                fma2(acc[i][2], ap, bp2);
                fma2(acc[i][3], ap, bp3);
            }
        }
        __syncthreads();
    }

    // unpack accumulators
    float c[8][8];
    #pragma unroll
    for (int i = 0; i < 8; i++)
        #pragma unroll
        for (int p = 0; p < 4; p++) {
            float2 v = unpack2(acc[i][p]);
            c[i][2*p]   = v.x;
            c[i][2*p+1] = v.y;
        }

    if (cmode == 0) {
        const int cn = bn + tx*8;
        float bi[8];
        #pragma unroll
        for (int q = 0; q < 8; q++)
            bi[q] = (bias != nullptr && (cn + q) < N) ? bias[cn + q] : 0.f;
        #pragma unroll
        for (int i = 0; i < 8; i++) {
            int row = bm + ty*8 + i;
            float* crow = C + (size_t)row * N;
            float4 v0 = make_float4(c[i][0]+bi[0], c[i][1]+bi[1],
                                    c[i][2]+bi[2], c[i][3]+bi[3]);
            float4 v1 = make_float4(c[i][4]+bi[4], c[i][5]+bi[5],
                                    c[i][6]+bi[6], c[i][7]+bi[7]);
            if (cn + 3 < N) *(float4*)(crow + cn)     = v0;
            if (cn + 7 < N) *(float4*)(crow + cn + 4) = v1;
        }
    } else {
        // transposed store: C_T[t][n][b]
        float* base = C + (size_t)(bm >> 7) * N * B_
                        + (size_t)(bn + tx*8) * B_ + ty*8;
        #pragma unroll
        for (int q = 0; q < 8; q++) {
            float4 v0 = make_float4(c[0][q], c[1][q], c[2][q], c[3][q]);
            float4 v1 = make_float4(c[4][q], c[5][q], c[6][q], c[7][q]);
            *(float4*)(base + (size_t)q*B_)     = v0;
            *(float4*)(base + (size_t)q*B_ + 4) = v1;
        }
    }
}

// ---------------------------------------------------------------------------
// Launch
// ---------------------------------------------------------------------------
extern "C" void kernel_launch(void* const* d_in, const int* in_sizes, int n_in,
                              void* d_out, int out_size)
{
    (void)in_sizes; (void)n_in; (void)out_size;

    const int*   inputs = (const int*)  d_in[0];  // [S, B]
    const float* hidden = (const float*)d_in[1];  // [L, B, H]
    const float* emb    = (const float*)d_in[2];  // [V, E]
    const float* W_ih   = (const float*)d_in[3];  // [L, H, H]
    const float* W_hh   = (const float*)d_in[4];  // [L, H, H]
    const float* b_hh   = (const float*)d_in[5];  // [L, H]
    const float* W_out  = (const float*)d_in[6];  // [V, H]
    const float* b_out  = (const float*)d_in[7];  // [V]
    float* out = (float*)d_out;                   // logits [S,B,V] then h_final [L,B,H]

    float *X, *H1, *H2, *P, *Wt;
    cudaGetSymbolAddress((void**)&X,  g_X);
    cudaGetSymbolAddress((void**)&H1, g_H1);
    cudaGetSymbolAddress((void**)&H2, g_H2);
    cudaGetSymbolAddress((void**)&P,  g_P);
    cudaGetSymbolAddress((void**)&Wt, g_Wt);
    float* P0 = P;
    float* P1 = P + 8*BH_;

    float* hfinal0 = out + (size_t)S_*B_*V_;
    float* hfinal1 = hfinal0 + BH_;

    // 0) transpose W_hh
    transpose_whh_kernel<<<(L_*H_*H_)/256, 256>>>(W_hh);

    // 1) X0^T = (emb[tok] @ W_ih0^T)^T   (gathered A, transposed store)
    {
        dim3 grid(H_/128, M_/128);
        sgemm2_kernel<<<grid, 256>>>(emb, inputs, W_ih, nullptr, X, H_, H_, 0, 1);
    }

    // 2) recurrence layer 1 (persistent)
    bar_reset_kernel<<<1, 1>>>();
    rec_persistent_kernel<<<NBLK, 256>>>(X, Wt, b_hh, hidden, P0, P1, H1, hfinal0);

    // 3) X1^T = (H1 @ W_ih1^T)^T   (A in [t][k][b], transposed store)
    {
        dim3 grid(H_/128, M_/128);
        sgemm2_kernel<<<grid, 256>>>(H1, nullptr, W_ih + H_*H_, nullptr, X, H_, H_, 1, 1);
    }

    // 4) recurrence layer 2 (persistent)
    bar_reset_kernel<<<1, 1>>>();
    rec_persistent_kernel<<<NBLK, 256>>>(X, Wt + H_*H_, b_hh + H_, hidden + BH_,
                                         P0, P1, H2, hfinal1);

    // 5) logits = H2 @ W_out^T + b_out   (A in [t][k][b], normal store)
    {
        dim3 grid((V_ + 127)/128, M_/128);
        sgemm2_kernel<<<grid, 256>>>(H2, nullptr, W_out, b_out, out, V_, H_, 1, 0);
    }
}